// round 15
// baseline (speedup 1.0000x reference)
#include <cuda_runtime.h>
#include <cstdint>

// GraphSage 2-layer, tf32 tensor-core (mma.sync m16n8k8).
// out[b][o] = relu( sum_k comb[b][k]*W[o][k] ), comb = [self | mean of 10 neigh]
// Phase 1: cp.async neighbor gathers, DEPTH-deep pipelined staging slots per
// warp (wait_group 1 keeps the next row's 40 lines in flight during reduce).
// Self row via one LDG.128 into a register (independent, scoreboard-covered).

#define DD     128
#define KN     10
#define B1_SZ  40960
#define B2_SZ  4096

#define KT     64      // W k-tile
#define CPAD   260     // comb row stride (floats); 260%32==4 -> conflict-free frags
#define WPAD   68      // Wsh row stride (floats);  68%32==4  -> conflict-free frags
#define SLOT_F (KN * DD)          // floats per staging slot (10 neighbor rows)

__device__ float g_h1[B1_SZ * DD];       // layer-1 hidden table (21 MB)

__device__ __forceinline__ uint32_t f2tf32(float f) {
    uint32_t u;
    asm("cvt.rna.tf32.f32 %0, %1;" : "=r"(u) : "f"(f));
    return u;
}

__device__ __forceinline__ float4 add4(float4 a, float4 b) {
    return make_float4(a.x + b.x, a.y + b.y, a.z + b.z, a.w + b.w);
}

__device__ __forceinline__ void cp16(uint32_t dst_smem, const void* src) {
    asm volatile("cp.async.cg.shared.global [%0], [%1], 16;"
                 :: "r"(dst_smem), "l"(src));
}
__device__ __forceinline__ void cp_commit() {
    asm volatile("cp.async.commit_group;");
}
__device__ __forceinline__ void cp_wait0() {
    asm volatile("cp.async.wait_group 0;" ::: "memory");
}
__device__ __forceinline__ void cp_wait1() {
    asm volatile("cp.async.wait_group 1;" ::: "memory");
}

__device__ __forceinline__ void mma_tf32(float& c0, float& c1, float& c2, float& c3,
                                         uint32_t a0, uint32_t a1, uint32_t a2, uint32_t a3,
                                         uint32_t b0, uint32_t b1) {
    asm volatile(
        "mma.sync.aligned.m16n8k8.row.col.f32.tf32.tf32.f32 "
        "{%0,%1,%2,%3}, {%4,%5,%6,%7}, {%8,%9}, {%0,%1,%2,%3};\n"
        : "+f"(c0), "+f"(c1), "+f"(c2), "+f"(c3)
        : "r"(a0), "r"(a1), "r"(a2), "r"(a3), "r"(b0), "r"(b1));
}

// Stage W[:, kt:kt+64] (fp32 in GMEM) as tf32 into Wsh[n][k]. CVTs hide under LDG.
__device__ __forceinline__ void stage_w(const float* __restrict__ W, float* Wsh,
                                        int kt, int tid) {
    #pragma unroll
    for (int it = 0; it < 8; it++) {
        const int e  = tid + it * 256;        // 0..2047
        const int n  = e >> 4;                // 0..127
        const int c4 = e & 15;                // float4 idx within k-tile
        float4 wv = __ldg(((const float4*)W) + n * 64 + (kt >> 2) + c4);
        uint4 wt = make_uint4(f2tf32(wv.x), f2tf32(wv.y), f2tf32(wv.z), f2tf32(wv.w));
        *((uint4*)(Wsh + n * WPAD + c4 * 4)) = wt;
    }
}

template <int BM_, int DEPTH>
__global__ __launch_bounds__(256, (DEPTH == 1) ? 2 : 1)
void sage_tf32(const float* __restrict__ table,   // [T][128]
               const float* __restrict__ W,       // [128][256] fp32
               const int*   __restrict__ nodes,   // [B]
               const int*   __restrict__ neigh,   // [B][10]
               float*       __restrict__ out)     // [B][128]
{
    constexpr int R    = BM_ / 8;          // rows per warp (phase 1)
    constexpr int NM   = BM_ / 16;         // 16-row m-tiles
    constexpr int NCOL = 128 / (8 / NM);   // output cols per warp
    constexpr int NT   = NCOL / 8;         // n-subtiles per warp

    extern __shared__ __align__(16) float smem[];
    float* comb  = smem;                           // [BM_][CPAD]
    float* Wsh   = smem + BM_ * CPAD;              // [128][WPAD]
    float* stage = Wsh + DD * WPAD;                // [8 warps][DEPTH][SLOT_F]

    const int tid  = threadIdx.x;
    const int warp = tid >> 5;
    const int lane = tid & 31;
    const int b0   = blockIdx.x * BM_;

    // stage W k-tile 0 (independent of comb; overlaps with gathers)
    stage_w(W, Wsh, 0, tid);

    // ================= Phase 1: pipelined cp.async gather + mean =============
    {
        float* mySlots = stage + warp * (DEPTH * SLOT_F);
        const uint32_t st0 =
            (uint32_t)__cvta_generic_to_shared(mySlots) + (uint32_t)(lane * 16);
        const int rw0 = b0 + warp * R;

        // prologue: issue row 0 neighbors + self
        {
            int idx[KN];
            #pragma unroll
            for (int k = 0; k < KN; k++) idx[k] = __ldg(neigh + rw0 * KN + k);
            #pragma unroll
            for (int c = 0; c < KN; c++)
                cp16(st0 + c * 512, table + (long long)idx[c] * DD + lane * 4);
            cp_commit();
        }
        float4 vcur = __ldg(((const float4*)table)
                            + (long long)__ldg(nodes + rw0) * 32 + lane);
        float4 vnxt = vcur;

        #pragma unroll
        for (int i = 0; i < R; i++) {
            const int cur = (DEPTH == 2) ? (i & 1) : 0;

            if (DEPTH == 2) {
                // issue row i+1 into the other slot, then wait for row i only
                if (i + 1 < R) {
                    const int nrow = rw0 + i + 1;
                    int nidx[KN];
                    #pragma unroll
                    for (int k = 0; k < KN; k++) nidx[k] = __ldg(neigh + nrow * KN + k);
                    const uint32_t stN = st0 + (uint32_t)(((i + 1) & 1) * SLOT_F * 4);
                    #pragma unroll
                    for (int c = 0; c < KN; c++)
                        cp16(stN + c * 512, table + (long long)nidx[c] * DD + lane * 4);
                    cp_commit();
                    vnxt = __ldg(((const float4*)table)
                                 + (long long)__ldg(nodes + nrow) * 32 + lane);
                    cp_wait1();
                } else {
                    cp_wait0();
                }
            } else {
                // depth 1: prefetch next indices before the drain wait
                int nidx[KN]; int nnode = 0;
                if (i + 1 < R) {
                    const int nrow = rw0 + i + 1;
                    nnode = __ldg(nodes + nrow);
                    #pragma unroll
                    for (int k = 0; k < KN; k++) nidx[k] = __ldg(neigh + nrow * KN + k);
                }
                cp_wait0();
                if (i + 1 < R) {
                    // re-issue into the single slot happens AFTER reduce below;
                    // stash indices in registers until then
                    #pragma unroll
                    for (int k = 0; k < KN; k++) ((int*)&vnxt)[0] = 0; // no-op keep
                    // reduce now, then issue (handled after reduce)
                    // store for post-reduce issue:
                    // (fall through; see post-reduce block)
                    // indices kept in nidx/nnode below via local copy
                    // -- implemented by duplicating issue after reduce --
                    // reduce:
                    const float4* sp = (const float4*)(mySlots) + lane;
                    float4 a0 = add4(sp[0],   sp[32]);
                    float4 a1 = add4(sp[64],  sp[96]);
                    float4 a2 = add4(sp[128], sp[160]);
                    float4 a3 = add4(sp[192], sp[224]);
                    float4 a4 = add4(sp[256], sp[288]);
                    float4 s  = add4(add4(add4(a0, a1), add4(a2, a3)), a4);
                    const float m = 1.0f / (float)KN;
                    uint4 sv = make_uint4(f2tf32(vcur.x), f2tf32(vcur.y),
                                          f2tf32(vcur.z), f2tf32(vcur.w));
                    uint4 av = make_uint4(f2tf32(s.x * m), f2tf32(s.y * m),
                                          f2tf32(s.z * m), f2tf32(s.w * m));
                    const int r = warp * R + i;
                    ((uint4*)(comb + r * CPAD))[lane]      = sv;
                    ((uint4*)(comb + r * CPAD + DD))[lane] = av;
                    // now issue next row into the slot
                    #pragma unroll
                    for (int c = 0; c < KN; c++)
                        cp16(st0 + c * 512, table + (long long)nidx[c] * DD + lane * 4);
                    cp_commit();
                    vcur = __ldg(((const float4*)table) + (long long)nnode * 32 + lane);
                    continue;   // reduce already done
                }
            }

            // reduce slot `cur` (depth-2 path, and depth-1 last iteration)
            {
                const float4* sp = (const float4*)(mySlots + cur * SLOT_F) + lane;
                float4 a0 = add4(sp[0],   sp[32]);
                float4 a1 = add4(sp[64],  sp[96]);
                float4 a2 = add4(sp[128], sp[160]);
                float4 a3 = add4(sp[192], sp[224]);
                float4 a4 = add4(sp[256], sp[288]);
                float4 s  = add4(add4(add4(a0, a1), add4(a2, a3)), a4);
                const float m = 1.0f / (float)KN;
                uint4 sv = make_uint4(f2tf32(vcur.x), f2tf32(vcur.y),
                                      f2tf32(vcur.z), f2tf32(vcur.w));
                uint4 av = make_uint4(f2tf32(s.x * m), f2tf32(s.y * m),
                                      f2tf32(s.z * m), f2tf32(s.w * m));
                const int r = warp * R + i;
                ((uint4*)(comb + r * CPAD))[lane]      = sv;
                ((uint4*)(comb + r * CPAD + DD))[lane] = av;
            }
            vcur = vnxt;
        }
    }
    __syncthreads();

    // ================= Phase 2: tensor-core GEMM =================
    const int g     = lane >> 2;
    const int tig   = lane & 3;
    const int mbase = (warp % NM) * 16;
    const int nbase = (warp / NM) * NCOL;

    float acc[NT][4];
    #pragma unroll
    for (int nt = 0; nt < NT; nt++)
        #pragma unroll
        for (int j = 0; j < 4; j++) acc[nt][j] = 0.f;

    #pragma unroll
    for (int tix = 0; tix < (2 * DD) / KT; tix++) {
        const int kt = tix * KT;
        #pragma unroll
        for (int k0 = 0; k0 < KT; k0 += 8) {
            const uint32_t* ap = (const uint32_t*)(comb + (mbase + g) * CPAD + kt + k0 + tig);
            uint32_t a0 = ap[0];
            uint32_t a1 = ap[8 * CPAD];
            uint32_t a2 = ap[4];
            uint32_t a3 = ap[8 * CPAD + 4];
            #pragma unroll
            for (int nt = 0; nt < NT; nt++) {
                const uint32_t* bp = (const uint32_t*)(Wsh + (nbase + nt * 8 + g) * WPAD + k0 + tig);
                mma_tf32(acc[nt][0], acc[nt][1], acc[nt][2], acc[nt][3],
                         a0, a1, a2, a3, bp[0], bp[4]);
            }
        }
        if (tix < (2 * DD) / KT - 1) {
            __syncthreads();               // all warps done reading Wsh
            stage_w(W, Wsh, kt + KT, tid);
            __syncthreads();               // Wsh tile ready
        }
    }

    // ================= Epilogue: ReLU + store =================
    #pragma unroll
    for (int nt = 0; nt < NT; nt++) {
        const int row = b0 + mbase + g;
        const int col = nbase + nt * 8 + 2 * tig;
        float2 v0 = make_float2(fmaxf(acc[nt][0], 0.f), fmaxf(acc[nt][1], 0.f));
        float2 v1 = make_float2(fmaxf(acc[nt][2], 0.f), fmaxf(acc[nt][3], 0.f));
        *(float2*)(out + (long long)row * DD + col)       = v0;
        *(float2*)(out + (long long)(row + 8) * DD + col) = v1;
    }
}

extern "C" void kernel_launch(void* const* d_in, const int* in_sizes, int n_in,
                              void* d_out, int out_size)
{
    const float* raw    = (const float*)d_in[0];
    const float* W1     = (const float*)d_in[1];
    const float* W2     = (const float*)d_in[2];
    const int*   nodes1 = (const int*)  d_in[3];
    const int*   neigh1 = (const int*)  d_in[4];
    const int*   nodes2 = (const int*)  d_in[5];
    const int*   neigh2 = (const int*)  d_in[6];
    float*       out    = (float*)d_out;

    float* h1 = nullptr;
    cudaGetSymbolAddress((void**)&h1, g_h1);

    const int smem64 = (64 * CPAD + DD * WPAD) * 4 + 8 * 2 * SLOT_F * 4; // 183,296 B
    const int smem16 = (16 * CPAD + DD * WPAD) * 4 + 8 * 1 * SLOT_F * 4; //  92,416 B

    static bool attr_done = false;
    if (!attr_done) {
        cudaFuncSetAttribute((const void*)&sage_tf32<64, 2>,
                             cudaFuncAttributeMaxDynamicSharedMemorySize, smem64);
        cudaFuncSetAttribute((const void*)&sage_tf32<16, 1>,
                             cudaFuncAttributeMaxDynamicSharedMemorySize, smem16);
        attr_done = true;
    }

    sage_tf32<64, 2><<<B1_SZ / 64, 256, smem64>>>(raw, W1, nodes1, neigh1, h1);
    sage_tf32<16, 1><<<B2_SZ / 16, 256, smem16>>>(h1,  W2, nodes2, neigh2, out);
}

// round 16
// speedup vs baseline: 1.0889x; 1.0889x over previous
#include <cuda_runtime.h>
#include <cstdint>

// GraphSage 2-layer, tf32 tensor-core (mma.sync m16n8k8), templated on BM.
// out[b][o] = relu( sum_k comb[b][k]*W[o][k] ), comb = [self | mean of 10 neigh]
// Phase 1: cp.async gathers pipelined at HALF-ROW granularity (groups of 5
// neighbor rows), depth-2 slots per warp; wait_group 1 keeps the next group
// in flight during every reduce. 2 blocks/SM maintained (109 KB smem).

#define DD     128
#define KN     10
#define B1_SZ  40960
#define B2_SZ  4096

#define KT     64      // W k-tile
#define CPAD   260     // comb row stride (floats); 260%32==4 -> conflict-free frags
#define WPAD   68      // Wsh row stride (floats);  68%32==4  -> conflict-free frags
#define GRP    5                   // neighbor rows per pipeline group
#define SLOT_F (GRP * DD)          // floats per staging slot (640)

__device__ float g_h1[B1_SZ * DD];       // layer-1 hidden table (21 MB)

__device__ __forceinline__ uint32_t f2tf32(float f) {
    uint32_t u;
    asm("cvt.rna.tf32.f32 %0, %1;" : "=r"(u) : "f"(f));
    return u;
}

__device__ __forceinline__ float4 add4(float4 a, float4 b) {
    return make_float4(a.x + b.x, a.y + b.y, a.z + b.z, a.w + b.w);
}

__device__ __forceinline__ void cp16(uint32_t dst_smem, const void* src) {
    asm volatile("cp.async.cg.shared.global [%0], [%1], 16;"
                 :: "r"(dst_smem), "l"(src));
}
__device__ __forceinline__ void cp_commit() {
    asm volatile("cp.async.commit_group;");
}
__device__ __forceinline__ void cp_wait0() {
    asm volatile("cp.async.wait_group 0;" ::: "memory");
}
__device__ __forceinline__ void cp_wait1() {
    asm volatile("cp.async.wait_group 1;" ::: "memory");
}

__device__ __forceinline__ void mma_tf32(float& c0, float& c1, float& c2, float& c3,
                                         uint32_t a0, uint32_t a1, uint32_t a2, uint32_t a3,
                                         uint32_t b0, uint32_t b1) {
    asm volatile(
        "mma.sync.aligned.m16n8k8.row.col.f32.tf32.tf32.f32 "
        "{%0,%1,%2,%3}, {%4,%5,%6,%7}, {%8,%9}, {%0,%1,%2,%3};\n"
        : "+f"(c0), "+f"(c1), "+f"(c2), "+f"(c3)
        : "r"(a0), "r"(a1), "r"(a2), "r"(a3), "r"(b0), "r"(b1));
}

// Stage W[:, kt:kt+64] (fp32 in GMEM) as tf32 into Wsh[n][k]. CVTs hide under LDG.
__device__ __forceinline__ void stage_w(const float* __restrict__ W, float* Wsh,
                                        int kt, int tid) {
    #pragma unroll
    for (int it = 0; it < 8; it++) {
        const int e  = tid + it * 256;        // 0..2047
        const int n  = e >> 4;                // 0..127
        const int c4 = e & 15;                // float4 idx within k-tile
        float4 wv = __ldg(((const float4*)W) + n * 64 + (kt >> 2) + c4);
        uint4 wt = make_uint4(f2tf32(wv.x), f2tf32(wv.y), f2tf32(wv.z), f2tf32(wv.w));
        *((uint4*)(Wsh + n * WPAD + c4 * 4)) = wt;
    }
}

template <int BM_>
__global__ __launch_bounds__(256, 2)
void sage_tf32(const float* __restrict__ table,   // [T][128]
               const float* __restrict__ W,       // [128][256] fp32
               const int*   __restrict__ nodes,   // [B]
               const int*   __restrict__ neigh,   // [B][10]
               float*       __restrict__ out)     // [B][128]
{
    constexpr int R    = BM_ / 8;          // rows per warp (phase 1)
    constexpr int NG   = 2 * R;            // pipeline groups per warp
    constexpr int NM   = BM_ / 16;         // 16-row m-tiles
    constexpr int NCOL = 128 / (8 / NM);   // output cols per warp
    constexpr int NT   = NCOL / 8;         // n-subtiles per warp

    extern __shared__ __align__(16) float smem[];
    float* comb  = smem;                           // [BM_][CPAD]
    float* Wsh   = smem + BM_ * CPAD;              // [128][WPAD]
    float* stage = Wsh + DD * WPAD;                // [8 warps][2][SLOT_F]

    const int tid  = threadIdx.x;
    const int warp = tid >> 5;
    const int lane = tid & 31;
    const int b0   = blockIdx.x * BM_;

    // stage W k-tile 0 (independent of comb; overlaps with gathers)
    stage_w(W, Wsh, 0, tid);

    // ============ Phase 1: half-row depth-2 cp.async gather + mean ==========
    {
        float* mySlots = stage + warp * (2 * SLOT_F);
        const uint32_t st0 =
            (uint32_t)__cvta_generic_to_shared(mySlots) + (uint32_t)(lane * 16);
        const int rw0 = b0 + warp * R;

        // self rows: gather all upfront into registers (independent loads)
        int nd[R];
        #pragma unroll
        for (int r = 0; r < R; r++) nd[r] = __ldg(nodes + rw0 + r);
        float4 vself[R];
        #pragma unroll
        for (int r = 0; r < R; r++)
            vself[r] = __ldg(((const float4*)table) + (long long)nd[r] * 32 + lane);

        // prologue: issue group 0 (row 0, neighbors 0..4) into slot 0
        #pragma unroll
        for (int c = 0; c < GRP; c++) {
            const int idx = __ldg(neigh + rw0 * KN + c);
            cp16(st0 + c * 512, table + (long long)idx * DD + lane * 4);
        }
        cp_commit();

        float4 part = make_float4(0.f, 0.f, 0.f, 0.f);
        #pragma unroll
        for (int j = 0; j < NG; j++) {
            if (j + 1 < NG) {
                // issue group j+1 into the other slot, keep it in flight
                const int nrow  = (j + 1) >> 1;
                const int nhalf = (j + 1) & 1;
                const uint32_t stN = st0 + (uint32_t)(((j + 1) & 1) * SLOT_F * 4);
                #pragma unroll
                for (int c = 0; c < GRP; c++) {
                    const int idx = __ldg(neigh + (rw0 + nrow) * KN + nhalf * GRP + c);
                    cp16(stN + c * 512, table + (long long)idx * DD + lane * 4);
                }
                cp_commit();
                cp_wait1();        // group j ready; group j+1 still in flight
            } else {
                cp_wait0();        // last group
            }

            // reduce slot j&1 (5 chunks; lane reads only its own 16B per chunk)
            const float4* sp = (const float4*)(mySlots + (j & 1) * SLOT_F) + lane;
            float4 s01 = add4(sp[0],  sp[32]);
            float4 s23 = add4(sp[64], sp[96]);
            float4 sum = add4(add4(s01, s23), sp[128]);

            if ((j & 1) == 0) {
                part = sum;
            } else {
                const int r = j >> 1;
                float4 s = add4(part, sum);
                const float m = 1.0f / (float)KN;
                uint4 sv = make_uint4(f2tf32(vself[r].x), f2tf32(vself[r].y),
                                      f2tf32(vself[r].z), f2tf32(vself[r].w));
                uint4 av = make_uint4(f2tf32(s.x * m), f2tf32(s.y * m),
                                      f2tf32(s.z * m), f2tf32(s.w * m));
                ((uint4*)(comb + (warp * R + r) * CPAD))[lane]      = sv;
                ((uint4*)(comb + (warp * R + r) * CPAD + DD))[lane] = av;
            }
        }
    }
    __syncthreads();

    // ================= Phase 2: tensor-core GEMM =================
    const int g     = lane >> 2;
    const int tig   = lane & 3;
    const int mbase = (warp % NM) * 16;
    const int nbase = (warp / NM) * NCOL;

    float acc[NT][4];
    #pragma unroll
    for (int nt = 0; nt < NT; nt++)
        #pragma unroll
        for (int j = 0; j < 4; j++) acc[nt][j] = 0.f;

    #pragma unroll
    for (int tix = 0; tix < (2 * DD) / KT; tix++) {
        const int kt = tix * KT;
        #pragma unroll
        for (int k0 = 0; k0 < KT; k0 += 8) {
            const uint32_t* ap = (const uint32_t*)(comb + (mbase + g) * CPAD + kt + k0 + tig);
            uint32_t a0 = ap[0];
            uint32_t a1 = ap[8 * CPAD];
            uint32_t a2 = ap[4];
            uint32_t a3 = ap[8 * CPAD + 4];
            #pragma unroll
            for (int nt = 0; nt < NT; nt++) {
                const uint32_t* bp = (const uint32_t*)(Wsh + (nbase + nt * 8 + g) * WPAD + k0 + tig);
                mma_tf32(acc[nt][0], acc[nt][1], acc[nt][2], acc[nt][3],
                         a0, a1, a2, a3, bp[0], bp[4]);
            }
        }
        if (tix < (2 * DD) / KT - 1) {
            __syncthreads();               // all warps done reading Wsh
            stage_w(W, Wsh, kt + KT, tid);
            __syncthreads();               // Wsh tile ready
        }
    }

    // ================= Epilogue: ReLU + store =================
    #pragma unroll
    for (int nt = 0; nt < NT; nt++) {
        const int row = b0 + mbase + g;
        const int col = nbase + nt * 8 + 2 * tig;
        float2 v0 = make_float2(fmaxf(acc[nt][0], 0.f), fmaxf(acc[nt][1], 0.f));
        float2 v1 = make_float2(fmaxf(acc[nt][2], 0.f), fmaxf(acc[nt][3], 0.f));
        *(float2*)(out + (long long)row * DD + col)       = v0;
        *(float2*)(out + (long long)(row + 8) * DD + col) = v1;
    }
}

extern "C" void kernel_launch(void* const* d_in, const int* in_sizes, int n_in,
                              void* d_out, int out_size)
{
    const float* raw    = (const float*)d_in[0];
    const float* W1     = (const float*)d_in[1];
    const float* W2     = (const float*)d_in[2];
    const int*   nodes1 = (const int*)  d_in[3];
    const int*   neigh1 = (const int*)  d_in[4];
    const int*   nodes2 = (const int*)  d_in[5];
    const int*   neigh2 = (const int*)  d_in[6];
    float*       out    = (float*)d_out;

    float* h1 = nullptr;
    cudaGetSymbolAddress((void**)&h1, g_h1);

    const int stageB = 8 * 2 * SLOT_F * 4;                            // 40,960 B
    const int smem32 = (32 * CPAD + DD * WPAD) * 4 + stageB;          // 109,056 B
    const int smem16 = (16 * CPAD + DD * WPAD) * 4 + stageB;          //  92,416 B

    static bool attr_done = false;
    if (!attr_done) {
        cudaFuncSetAttribute(sage_tf32<32>,
                             cudaFuncAttributeMaxDynamicSharedMemorySize, smem32);
        cudaFuncSetAttribute(sage_tf32<16>,
                             cudaFuncAttributeMaxDynamicSharedMemorySize, smem16);
        attr_done = true;
    }

    sage_tf32<32><<<B1_SZ / 32, 256, smem32>>>(raw, W1, nodes1, neigh1, h1);
    sage_tf32<16><<<B2_SZ / 16, 256, smem16>>>(h1,  W2, nodes2, neigh2, out);
}